// round 9
// baseline (speedup 1.0000x reference)
#include <cuda_runtime.h>
#include <float.h>
#include <math.h>

// CropRoi: f (4,64,32,32,32) f32; proposals (96,8) f32; out (96,64,7,7,7) f32.
// Box: c0 = max(floor((c-s/2)/4),0), c1 = min(ceil((c+s/2)/4),32); L in [2,13].
// Adaptive windows per axis: size 1..3, always in-range -> plain max.
//
// R8 lesson: the dynamic triple loop makes every warp pay max-lane trip count
// plus ~12 instr/iter of loop machinery (165 instr/warp measured). Fix: keep
// the R2 layout (grid 96x64, one thread per bin) but compute the window max
// STRAIGHT-LINE with clamped taps {0, min(1,n), n} per axis -- duplicate taps
// are harmless under fmax, no branches, MLP = tap count. Warp-uniform fast
// path (__all_sync): all windows <= 2 wide -> 8 taps; else 27 taps.

#define RBINS 7
#define NBINS 343
#define FDIM 32
#define MAXN 128

__device__ int g_desc[MAXN * NBINS];
__device__ int g_base[MAXN];

__global__ void precompute_kernel(const float* __restrict__ props)
{
    const int n = blockIdx.x;
    const int o = threadIdx.x;
    const float* p = props + n * 8;

    int c0[3], L[3];
#pragma unroll
    for (int ax = 0; ax < 3; ++ax) {
        const float ce = p[2 + ax], si = p[5 + ax];
        int lo = (int)floorf((ce - si * 0.5f) * 0.25f);
        int hi = (int)ceilf ((ce + si * 0.5f) * 0.25f);
        lo = max(lo, 0); hi = min(hi, FDIM);
        c0[ax] = lo;
        L[ax]  = max(hi - lo, 0);
    }

    if (o == 0) {
        const int b = (int)p[0];
        g_base[n] = ((b * 64) << 15) +
                    ((c0[0] * FDIM + c0[1]) * FDIM + c0[2]);
    }

    if (o < NBINS) {
        const int k = o % RBINS;
        const int j = (o / RBINS) % RBINS;
        const int i = o / (RBINS * RBINS);

        const int ds = (i * L[0]) / RBINS, de = ((i + 1) * L[0] + RBINS - 1) / RBINS;
        const int hs = (j * L[1]) / RBINS, he = ((j + 1) * L[1] + RBINS - 1) / RBINS;
        const int ws = (k * L[2]) / RBINS, we = ((k + 1) * L[2] + RBINS - 1) / RBINS;

        const int start = (ds * FDIM + hs) * FDIM + ws;                 // 15 bits
        const int nd = de - ds - 1, nh = he - hs - 1, nw = we - ws - 1; // 0..2
        g_desc[n * NBINS + o] = start | (nd << 15) | (nh << 17) | (nw << 19);
    }
}

__global__ __launch_bounds__(352)
void pool_kernel(const float* __restrict__ f, float* __restrict__ out)
{
    const int n = blockIdx.x;   // proposal
    const int c = blockIdx.y;   // channel
    const int tid = threadIdx.x;
    const int t = min(tid, NBINS - 1);   // tail lanes shadow bin 342 (no store)

    const int desc  = g_desc[n * NBINS + t];
    const int start =  desc        & 0x7FFF;
    const int nd    = (desc >> 15) & 3;
    const int nh    = (desc >> 17) & 3;
    const int nw    = (desc >> 19) & 3;

    const float* base = f + g_base[n] + (c << 15) + start;

    const int d2 = nd << 10, h2 = nh << 5, w2 = nw;

    float m;
    if (__all_sync(0xFFFFFFFFu, (nd | nh | nw) <= 1)) {
        // all windows in this warp are <= 2 wide: 8 clamped taps
        const float a0 = base[0],       a1 = base[w2];
        const float a2 = base[h2],      a3 = base[h2 + w2];
        const float a4 = base[d2],      a5 = base[d2 + w2];
        const float a6 = base[d2 + h2], a7 = base[d2 + h2 + w2];
        m = fmaxf(fmaxf(fmaxf(a0, a1), fmaxf(a2, a3)),
                  fmaxf(fmaxf(a4, a5), fmaxf(a6, a7)));
    } else {
        // general case: 27 clamped taps (duplicates harmless under max)
        const int d1 = min(nd, 1) << 10;
        const int h1 = min(nh, 1) << 5;
        const int w1 = min(nw, 1);
        const int dd[3] = {0, d1, d2};
        const int hh[3] = {0, h1, h2};
        const int ww[3] = {0, w1, w2};

        float v[27];
#pragma unroll
        for (int a = 0; a < 3; ++a)
#pragma unroll
            for (int b = 0; b < 3; ++b)
#pragma unroll
                for (int e = 0; e < 3; ++e)
                    v[(a * 3 + b) * 3 + e] = base[dd[a] + hh[b] + ww[e]];

        m = v[0];
#pragma unroll
        for (int q = 1; q < 27; ++q)
            m = fmaxf(m, v[q]);
    }

    if (tid < NBINS)
        out[(size_t)(n * 64 + c) * NBINS + tid] = m;
}

extern "C" void kernel_launch(void* const* d_in, const int* in_sizes, int n_in,
                              void* d_out, int out_size)
{
    const float* f     = (const float*)d_in[0];
    const float* props = (const float*)d_in[2];
    float* out = (float*)d_out;

    const int N = in_sizes[2] / 8;   // 96

    precompute_kernel<<<N, 352>>>(props);
    pool_kernel<<<dim3(N, 64), 352>>>(f, out);
}